// round 1
// baseline (speedup 1.0000x reference)
#include <cuda_runtime.h>

// Problem constants (fixed shapes from setup_inputs)
#define B 2
#define D 160
#define H 160
#define W 160
#define NVOX (B * D * H * W)          // 8,192,000
#define NROWS (B * D * H)             // 51,200
#define HW (H * W)                    // 25,600
#define K3_SEGS 5
#define K3_SEGLEN 32
#define K3_BLOCKS (B * H * K3_SEGS)   // 1600

// SSIM constants (faithful to source: C1 = K1 / data_range^2)
#define C1F 5.9604644775390625e-10f   // 0.01 / 4096^2
#define C2F 1.7881393432617188e-09f   // 0.03 / 4096^2
#define INV_WIN3 (1.0f / 1331.0f)

// Scratch: 5 quantity planes each, ping-pong between passes.
__device__ float g_bufA[5 * NVOX];    // after W-pass
__device__ float g_bufB[5 * NVOX];    // after H-pass
__device__ float g_l1part[NROWS];
__device__ float g_ssimpart[K3_BLOCKS];

// ---------------------------------------------------------------------------
// K1: box-sum along W for x, y, x^2, y^2, x*y  +  smooth-L1 block partials.
// One block per contiguous row of 160 elements.
// ---------------------------------------------------------------------------
__global__ __launch_bounds__(W) void k1_wpass(const float* __restrict__ x,
                                              const float* __restrict__ y) {
    __shared__ float sx[W];
    __shared__ float sy[W];
    __shared__ float red[W];

    const int row = blockIdx.x;       // 0 .. NROWS-1
    const int w = threadIdx.x;        // 0 .. 159
    const int base = row * W;

    const float xv = x[base + w];
    const float yv = y[base + w];
    sx[w] = xv;
    sy[w] = yv;

    // smooth L1 contribution
    float dd = fabsf(xv - yv);
    float l1 = (dd < 1.0f) ? 0.5f * dd * dd : dd - 0.5f;

    __syncthreads();

    float ax = 0.f, ay = 0.f, axx = 0.f, ayy = 0.f, axy = 0.f;
#pragma unroll
    for (int j = -5; j <= 5; j++) {
        int ww = w + j;
        if (ww >= 0 && ww < W) {
            float a = sx[ww];
            float b = sy[ww];
            ax += a;
            ay += b;
            axx += a * a;
            ayy += b * b;
            axy += a * b;
        }
    }

    const int idx = base + w;
    g_bufA[0 * NVOX + idx] = ax;
    g_bufA[1 * NVOX + idx] = ay;
    g_bufA[2 * NVOX + idx] = axx;
    g_bufA[3 * NVOX + idx] = ayy;
    g_bufA[4 * NVOX + idx] = axy;

    // deterministic block reduction of l1 over 160 threads
    red[w] = l1;
    __syncthreads();
    if (w < 80) red[w] += red[w + 80];
    __syncthreads();
    if (w < 40) red[w] += red[w + 40];
    __syncthreads();
    if (w < 20) red[w] += red[w + 20];
    __syncthreads();
    if (w < 10) red[w] += red[w + 10];
    __syncthreads();
    if (w < 5) red[w] += red[w + 5];
    __syncthreads();
    if (w == 0) {
        g_l1part[row] = red[0] + red[1] + red[2] + red[3] + red[4];
    }
}

// ---------------------------------------------------------------------------
// K2: box-sum along H with per-thread running sum.
// grid: (B*D, 5 quantities), block: 160 threads (one per w).
// ---------------------------------------------------------------------------
__global__ __launch_bounds__(W) void k2_hpass() {
    const int bd = blockIdx.x;        // 0 .. B*D-1
    const int q = blockIdx.y;         // 0 .. 4
    const int w = threadIdx.x;

    const float* __restrict__ in = g_bufA + q * NVOX + bd * HW;
    float* __restrict__ out = g_bufB + q * NVOX + bd * HW;

    float s = 0.f;
#pragma unroll
    for (int h = 0; h < 6; h++) s += in[h * W + w];

#pragma unroll 4
    for (int h = 0; h < H; h++) {
        out[h * W + w] = s;
        if (h + 6 < H) s += in[(h + 6) * W + w];
        if (h >= 5) s -= in[(h - 5) * W + w];
    }
}

// ---------------------------------------------------------------------------
// K3: box-sum along D with 5 per-thread running sums + SSIM per voxel + block
// reduction of the clipped SSIM loss.
// grid: (B * H * K3_SEGS) blocks, block: 160 threads (one per w).
// ---------------------------------------------------------------------------
__global__ __launch_bounds__(W) void k3_dpass_ssim() {
    __shared__ float red[W];

    const int bid = blockIdx.x;
    const int seg = bid % K3_SEGS;
    const int h = (bid / K3_SEGS) % H;
    const int b = bid / (K3_SEGS * H);
    const int w = threadIdx.x;

    const int d0 = seg * K3_SEGLEN;
    // linear index at depth d: b*D*H*W + d*H*W + h*W + w
    const int colbase = b * (D * HW) + h * W + w;

    const float* __restrict__ p0 = g_bufB + 0 * NVOX;
    const float* __restrict__ p1 = g_bufB + 1 * NVOX;
    const float* __restrict__ p2 = g_bufB + 2 * NVOX;
    const float* __restrict__ p3 = g_bufB + 3 * NVOX;
    const float* __restrict__ p4 = g_bufB + 4 * NVOX;

    float s0 = 0.f, s1 = 0.f, s2 = 0.f, s3 = 0.f, s4 = 0.f;
    {
        int lo = d0 - 5;
        if (lo < 0) lo = 0;
        int hi = d0 + 5;
        if (hi > D - 1) hi = D - 1;
        for (int d = lo; d <= hi; d++) {
            int id = colbase + d * HW;
            s0 += p0[id];
            s1 += p1[id];
            s2 += p2[id];
            s3 += p3[id];
            s4 += p4[id];
        }
    }

    float acc = 0.f;
#pragma unroll 4
    for (int i = 0; i < K3_SEGLEN; i++) {
        const int d = d0 + i;

        // SSIM at this voxel from current window sums
        float mux = s0 * INV_WIN3;
        float muy = s1 * INV_WIN3;
        float mux2 = mux * mux;
        float muy2 = muy * muy;
        float muxy = mux * muy;
        float sxx = s2 * INV_WIN3 - mux2;
        float syy = s3 * INV_WIN3 - muy2;
        float sxy = s4 * INV_WIN3 - muxy;
        float num = (2.f * muxy + C1F) * (2.f * sxy + C2F);
        float den = (mux2 + muy2 + C1F) * (sxx + syy + C2F);
        float ssim = num / (den + 1e-8f);
        float loss = (1.f - ssim) * 0.5f;
        loss = fminf(fmaxf(loss, 0.f), 1.f);
        acc += loss;

        int dn = d + 6;
        int dp = d - 5;
        if (dn < D) {
            int id = colbase + dn * HW;
            s0 += p0[id];
            s1 += p1[id];
            s2 += p2[id];
            s3 += p3[id];
            s4 += p4[id];
        }
        if (dp >= 0) {
            int id = colbase + dp * HW;
            s0 -= p0[id];
            s1 -= p1[id];
            s2 -= p2[id];
            s3 -= p3[id];
            s4 -= p4[id];
        }
    }

    // deterministic block reduction over 160 threads
    red[w] = acc;
    __syncthreads();
    if (w < 80) red[w] += red[w + 80];
    __syncthreads();
    if (w < 40) red[w] += red[w + 40];
    __syncthreads();
    if (w < 20) red[w] += red[w + 20];
    __syncthreads();
    if (w < 10) red[w] += red[w + 10];
    __syncthreads();
    if (w < 5) red[w] += red[w + 5];
    __syncthreads();
    if (w == 0) {
        g_ssimpart[bid] = red[0] + red[1] + red[2] + red[3] + red[4];
    }
}

// ---------------------------------------------------------------------------
// K4: deterministic final reduction in double precision.
// ---------------------------------------------------------------------------
__global__ __launch_bounds__(256) void k4_final(float* __restrict__ out) {
    __shared__ double sh[256];
    const int t = threadIdx.x;

    double a = 0.0;
    for (int i = t; i < NROWS; i += 256) a += (double)g_l1part[i];
    double bsum = 0.0;
    for (int i = t; i < K3_BLOCKS; i += 256) bsum += (double)g_ssimpart[i];

    sh[t] = a;
    __syncthreads();
#pragma unroll
    for (int s = 128; s > 0; s >>= 1) {
        if (t < s) sh[t] += sh[t + s];
        __syncthreads();
    }
    double l1sum = sh[0];
    __syncthreads();

    sh[t] = bsum;
    __syncthreads();
#pragma unroll
    for (int s = 128; s > 0; s >>= 1) {
        if (t < s) sh[t] += sh[t + s];
        __syncthreads();
    }

    if (t == 0) {
        double ssimsum = sh[0];
        double n = (double)NVOX;
        out[0] = (float)(0.85 * (ssimsum / n) + 0.15 * (l1sum / n));
    }
}

// ---------------------------------------------------------------------------
extern "C" void kernel_launch(void* const* d_in, const int* in_sizes, int n_in,
                              void* d_out, int out_size) {
    const float* pred = (const float*)d_in[0];
    const float* target = (const float*)d_in[1];
    float* out = (float*)d_out;

    k1_wpass<<<NROWS, W>>>(pred, target);
    dim3 g2(B * D, 5);
    k2_hpass<<<g2, W>>>();
    k3_dpass_ssim<<<K3_BLOCKS, W>>>();
    k4_final<<<1, 256>>>(out);
}

// round 3
// speedup vs baseline: 1.8212x; 1.8212x over previous
#include <cuda_runtime.h>

// Fixed shapes
#define B 2
#define D 160
#define H 160
#define W 160
#define NVOX (B * D * H * W)          // 8,192,000
#define HW (H * W)                    // 25,600

#define HSEGS 4
#define HSEG_LEN (H / HSEGS)          // 40
#define A_BLOCKS (B * D * HSEGS)      // 1280

#define K3_SEGS 2
#define K3_SEGLEN 80
#define K3_BLOCKS (B * H * K3_SEGS)   // 640

// SSIM constants (faithful: C1 = K1 / data_range^2)
#define C1F 5.9604644775390625e-10f   // 0.01 / 4096^2
#define C2F 1.7881393432617188e-09f   // 0.03 / 4096^2
#define INV_WIN3 (1.0f / 1331.0f)

// Scratch: 5 quantity planes after fused W+H pass.
__device__ float g_bufB[5 * NVOX];
__device__ float g_l1part[A_BLOCKS];
__device__ float g_ssimpart[K3_BLOCKS];

// ---------------------------------------------------------------------------
// Kernel A: fused W-pass + H-pass (box sums of x, y, x^2, y^2, xy over the
// 11-wide windows in w and h), streaming along h with an 11-slot smem ring of
// w-summed rows and per-thread running h-sums. Also accumulates smooth-L1.
// grid = B*D*HSEGS blocks, 160 threads (one per w).
// ---------------------------------------------------------------------------
__global__ __launch_bounds__(W) void kA_wh(const float* __restrict__ x,
                                           const float* __restrict__ y) {
    __shared__ float sx[2][W];
    __shared__ float sy[2][W];
    __shared__ float ring[11][5][W];   // [slot][quantity][w], per-thread use only

    const int bx = blockIdx.x;
    const int seg = bx % HSEGS;
    const int d = (bx / HSEGS) % D;
    const int b = bx / (HSEGS * D);
    const int w = threadIdx.x;

    const int h0 = seg * HSEG_LEN;
    const int pb = (b * D + d) * HW;   // plane base

    // prefetch first row (r = h0-5)
    int r = h0 - 5;
    float px = 0.f, py = 0.f;
    if (r >= 0) {                       // r < H always here
        px = x[pb + r * W + w];
        py = y[pb + r * W + w];
    }

    float s0 = 0.f, s1 = 0.f, s2 = 0.f, s3 = 0.f, s4 = 0.f;
    float l1acc = 0.f;
    int buf = 0;
    int wslot = 0;
    int sslot = 0;

    // 50 ingest steps: rows h0-5 .. h0+44. Outputs start at step 10.
    for (int t = 0; t < HSEG_LEN + 10; t++) {
        // stage the prefetched row (row index r)
        sx[buf][w] = px;
        sy[buf][w] = py;

        const bool curv = (r >= 0) && (r < H);
        const bool outrow = (r >= h0) && (r < h0 + HSEG_LEN);

        // issue prefetch of next row (consumed next iteration)
        {
            int rn = r + 1;
            if (rn >= 0 && rn < H) {
                px = x[pb + rn * W + w];
                py = y[pb + rn * W + w];
            } else {
                px = 0.f;
                py = 0.f;
            }
        }

        __syncthreads();

        if (curv) {
            // W-pass: 11-tap sums from the staged row
            float ax = 0.f, ay = 0.f, axx = 0.f, ayy = 0.f, axy = 0.f;
            const float* __restrict__ rx = sx[buf];
            const float* __restrict__ ry = sy[buf];
#pragma unroll
            for (int j = -5; j <= 5; j++) {
                int ww = w + j;
                if (ww >= 0 && ww < W) {
                    float a = rx[ww];
                    float c = ry[ww];
                    ax += a;
                    ay += c;
                    axx = fmaf(a, a, axx);
                    ayy = fmaf(c, c, ayy);
                    axy = fmaf(a, c, axy);
                }
            }
            ring[wslot][0][w] = ax;
            ring[wslot][1][w] = ay;
            ring[wslot][2][w] = axx;
            ring[wslot][3][w] = ayy;
            ring[wslot][4][w] = axy;
            s0 += ax; s1 += ay; s2 += axx; s3 += ayy; s4 += axy;

            if (outrow) {
                // smooth-L1 for this element (counted exactly once globally)
                float a0 = rx[w];
                float c0 = ry[w];
                float dd = fabsf(a0 - c0);
                l1acc += (dd < 1.0f) ? 0.5f * dd * dd : dd - 0.5f;
            }
        }
        wslot = (wslot == 10) ? 0 : wslot + 1;

        if (t >= 10) {
            const int h = h0 + t - 10;   // output row; window = h-5..h+5 == ingested
            const int oi = pb + h * W + w;
            g_bufB[0 * NVOX + oi] = s0;
            g_bufB[1 * NVOX + oi] = s1;
            g_bufB[2 * NVOX + oi] = s2;
            g_bufB[3 * NVOX + oi] = s3;
            g_bufB[4 * NVOX + oi] = s4;

            const int hs = h - 5;
            if (hs >= 0) {
                s0 -= ring[sslot][0][w];
                s1 -= ring[sslot][1][w];
                s2 -= ring[sslot][2][w];
                s3 -= ring[sslot][3][w];
                s4 -= ring[sslot][4][w];
            }
            sslot = (sslot == 10) ? 0 : sslot + 1;
        }

        buf ^= 1;
        r++;                            // advance ingest row (R2 bug fix)
        __syncthreads();
    }

    // deterministic block reduction of l1acc (reuse sx as scratch)
    float* red = sx[0];
    red[w] = l1acc;
    __syncthreads();
    if (w < 80) red[w] += red[w + 80];
    __syncthreads();
    if (w < 40) red[w] += red[w + 40];
    __syncthreads();
    if (w < 20) red[w] += red[w + 20];
    __syncthreads();
    if (w < 10) red[w] += red[w + 10];
    __syncthreads();
    if (w < 5) red[w] += red[w + 5];
    __syncthreads();
    if (w == 0) {
        g_l1part[bx] = red[0] + red[1] + red[2] + red[3] + red[4];
    }
}

// ---------------------------------------------------------------------------
// Kernel B: box-sum along D with 5 per-thread running sums + SSIM per voxel +
// block reduction of the clipped SSIM loss.
// grid = B*H*K3_SEGS blocks, 160 threads (one per w).
// ---------------------------------------------------------------------------
__global__ __launch_bounds__(W) void kB_dpass_ssim() {
    __shared__ float red[W];

    const int bid = blockIdx.x;
    const int seg = bid % K3_SEGS;
    const int h = (bid / K3_SEGS) % H;
    const int b = bid / (K3_SEGS * H);
    const int w = threadIdx.x;

    const int d0 = seg * K3_SEGLEN;
    const int colbase = b * (D * HW) + h * W + w;

    const float* __restrict__ p0 = g_bufB + 0 * NVOX;
    const float* __restrict__ p1 = g_bufB + 1 * NVOX;
    const float* __restrict__ p2 = g_bufB + 2 * NVOX;
    const float* __restrict__ p3 = g_bufB + 3 * NVOX;
    const float* __restrict__ p4 = g_bufB + 4 * NVOX;

    float s0 = 0.f, s1 = 0.f, s2 = 0.f, s3 = 0.f, s4 = 0.f;
    {
        int lo = d0 - 5;
        if (lo < 0) lo = 0;
        int hi = d0 + 5;
        if (hi > D - 1) hi = D - 1;
        for (int d = lo; d <= hi; d++) {
            int id = colbase + d * HW;
            s0 += p0[id];
            s1 += p1[id];
            s2 += p2[id];
            s3 += p3[id];
            s4 += p4[id];
        }
    }

    float acc = 0.f;
#pragma unroll 4
    for (int i = 0; i < K3_SEGLEN; i++) {
        const int d = d0 + i;

        float mux = s0 * INV_WIN3;
        float muy = s1 * INV_WIN3;
        float mux2 = mux * mux;
        float muy2 = muy * muy;
        float muxy = mux * muy;
        float sxx = s2 * INV_WIN3 - mux2;
        float syy = s3 * INV_WIN3 - muy2;
        float sxy = s4 * INV_WIN3 - muxy;
        float num = (2.f * muxy + C1F) * (2.f * sxy + C2F);
        float den = (mux2 + muy2 + C1F) * (sxx + syy + C2F);
        float ssim = num / (den + 1e-8f);
        float loss = (1.f - ssim) * 0.5f;
        loss = fminf(fmaxf(loss, 0.f), 1.f);
        acc += loss;

        int dn = d + 6;
        int dp = d - 5;
        if (dn < D) {
            int id = colbase + dn * HW;
            s0 += p0[id];
            s1 += p1[id];
            s2 += p2[id];
            s3 += p3[id];
            s4 += p4[id];
        }
        if (dp >= 0) {
            int id = colbase + dp * HW;
            s0 -= p0[id];
            s1 -= p1[id];
            s2 -= p2[id];
            s3 -= p3[id];
            s4 -= p4[id];
        }
    }

    red[w] = acc;
    __syncthreads();
    if (w < 80) red[w] += red[w + 80];
    __syncthreads();
    if (w < 40) red[w] += red[w + 40];
    __syncthreads();
    if (w < 20) red[w] += red[w + 20];
    __syncthreads();
    if (w < 10) red[w] += red[w + 10];
    __syncthreads();
    if (w < 5) red[w] += red[w + 5];
    __syncthreads();
    if (w == 0) {
        g_ssimpart[bid] = red[0] + red[1] + red[2] + red[3] + red[4];
    }
}

// ---------------------------------------------------------------------------
// Kernel C: final deterministic reduction (small partial arrays now).
// ---------------------------------------------------------------------------
__global__ __launch_bounds__(256) void kC_final(float* __restrict__ out) {
    __shared__ double sh[256];
    const int t = threadIdx.x;

    double a = 0.0;
    for (int i = t; i < A_BLOCKS; i += 256) a += (double)g_l1part[i];
    double bsum = 0.0;
    for (int i = t; i < K3_BLOCKS; i += 256) bsum += (double)g_ssimpart[i];

    sh[t] = a;
    __syncthreads();
#pragma unroll
    for (int s = 128; s > 0; s >>= 1) {
        if (t < s) sh[t] += sh[t + s];
        __syncthreads();
    }
    double l1sum = sh[0];
    __syncthreads();

    sh[t] = bsum;
    __syncthreads();
#pragma unroll
    for (int s = 128; s > 0; s >>= 1) {
        if (t < s) sh[t] += sh[t + s];
        __syncthreads();
    }

    if (t == 0) {
        double ssimsum = sh[0];
        double n = (double)NVOX;
        out[0] = (float)(0.85 * (ssimsum / n) + 0.15 * (l1sum / n));
    }
}

// ---------------------------------------------------------------------------
extern "C" void kernel_launch(void* const* d_in, const int* in_sizes, int n_in,
                              void* d_out, int out_size) {
    const float* pred = (const float*)d_in[0];
    const float* target = (const float*)d_in[1];
    float* out = (float*)d_out;

    kA_wh<<<A_BLOCKS, W>>>(pred, target);
    kB_dpass_ssim<<<K3_BLOCKS, W>>>();
    kC_final<<<1, 256>>>(out);
}

// round 4
// speedup vs baseline: 1.9126x; 1.0502x over previous
#include <cuda_runtime.h>

// Fixed shapes
#define B 2
#define D 160
#define H 160
#define W 160
#define NVOX (B * D * H * W)          // 8,192,000
#define HW (H * W)                    // 25,600

#define HSEGS 4
#define HSEG_LEN (H / HSEGS)          // 40
#define A_BLOCKS (B * D * HSEGS)      // 1280

#define K3_SEGS 4
#define K3_SEGLEN 40
#define HPAIRS (H / 2)                // 80
#define K3_BLOCKS (B * HPAIRS * K3_SEGS)  // 2560 blocks... (see grid) actually 2*80*4 = 640
#define K3_THREADS 320

// SSIM constants (faithful: C1 = K1 / data_range^2)
#define C1F 5.9604644775390625e-10f   // 0.01 / 4096^2
#define C2F 1.7881393432617188e-09f   // 0.03 / 4096^2
#define INV_WIN3 (1.0f / 1331.0f)

// Scratch: 5 quantity planes after fused W+H pass.
__device__ float g_bufB[5 * NVOX];
__device__ float g_l1part[A_BLOCKS];
__device__ float g_ssimpart[2 * HPAIRS * K3_SEGS];

// ---------------------------------------------------------------------------
// Kernel A: fused W-pass + H-pass box sums (x, y, x^2, y^2, xy), streaming
// along h. Zero-padded staging rows -> unconditional 11-tap windows; ring of
// w-summed rows is thread-private smem; ONE barrier per row via double buffer.
// grid = B*D*HSEGS blocks, 160 threads (one per w).
// ---------------------------------------------------------------------------
__global__ __launch_bounds__(W) void kA_wh(const float* __restrict__ x,
                                           const float* __restrict__ y) {
    __shared__ float sx[2][W + 10];
    __shared__ float sy[2][W + 10];
    __shared__ float ring[11][5][W];   // [slot][quantity][w] — thread-private by w

    const int bx = blockIdx.x;
    const int seg = bx % HSEGS;
    const int d = (bx / HSEGS) % D;
    const int b = bx / (HSEGS * D);
    const int w = threadIdx.x;

    const int h0 = seg * HSEG_LEN;
    const int pb = (b * D + d) * HW;   // plane base

    // zero the pads once (never rewritten)
    if (w < 10) {
        int p = (w < 5) ? w : (W + w);   // 0..4 and W+5..W+9
        sx[0][p] = 0.f; sx[1][p] = 0.f;
        sy[0][p] = 0.f; sy[1][p] = 0.f;
    }

    // prefetch first row (r = h0-5)
    int r = h0 - 5;
    float px = 0.f, py = 0.f;
    if (r >= 0) {
        px = x[pb + r * W + w];
        py = y[pb + r * W + w];
    }
    __syncthreads();   // pads visible

    float s0 = 0.f, s1 = 0.f, s2 = 0.f, s3 = 0.f, s4 = 0.f;
    float l1acc = 0.f;
    int buf = 0;
    int wslot = 0;
    int sslot = 0;

    // 50 ingest steps: rows h0-5 .. h0+44. Outputs start at step 10.
    for (int t = 0; t < HSEG_LEN + 10; t++) {
        sx[buf][5 + w] = px;
        sy[buf][5 + w] = py;

        const bool outrow = (r >= h0) && (r < h0 + HSEG_LEN);

        // prefetch next row (consumed next iteration)
        {
            int rn = r + 1;
            if (rn >= 0 && rn < H) {
                px = x[pb + rn * W + w];
                py = y[pb + rn * W + w];
            } else {
                px = 0.f;
                py = 0.f;
            }
        }

        __syncthreads();   // single barrier per row (double-buffered staging)

        // W-pass: unconditional 11-tap sums from the padded staged row
        {
            const float* __restrict__ rx = sx[buf];
            const float* __restrict__ ry = sy[buf];
            float ax = 0.f, ay = 0.f, axx = 0.f, ayy = 0.f, axy = 0.f;
#pragma unroll
            for (int jj = 0; jj <= 10; jj++) {
                float a = rx[w + jj];
                float c = ry[w + jj];
                ax += a;
                ay += c;
                axx = fmaf(a, a, axx);
                ayy = fmaf(c, c, ayy);
                axy = fmaf(a, c, axy);
            }
            ring[wslot][0][w] = ax;
            ring[wslot][1][w] = ay;
            ring[wslot][2][w] = axx;
            ring[wslot][3][w] = ayy;
            ring[wslot][4][w] = axy;
            s0 += ax; s1 += ay; s2 += axx; s3 += ayy; s4 += axy;

            if (outrow) {
                float a0 = rx[5 + w];
                float c0 = ry[5 + w];
                float dd = fabsf(a0 - c0);
                l1acc += (dd < 1.0f) ? 0.5f * dd * dd : dd - 0.5f;
            }
        }
        wslot = (wslot == 10) ? 0 : wslot + 1;

        if (t >= 10) {
            const int h = h0 + t - 10;
            const int oi = pb + h * W + w;
            g_bufB[0 * NVOX + oi] = s0;
            g_bufB[1 * NVOX + oi] = s1;
            g_bufB[2 * NVOX + oi] = s2;
            g_bufB[3 * NVOX + oi] = s3;
            g_bufB[4 * NVOX + oi] = s4;

            if (h - 5 >= 0) {
                s0 -= ring[sslot][0][w];
                s1 -= ring[sslot][1][w];
                s2 -= ring[sslot][2][w];
                s3 -= ring[sslot][3][w];
                s4 -= ring[sslot][4][w];
            }
            sslot = (sslot == 10) ? 0 : sslot + 1;
        }

        buf ^= 1;
        r++;
    }

    // deterministic block reduction of l1acc
    __syncthreads();
    float* red = sx[0];
    red[w] = l1acc;
    __syncthreads();
    if (w < 80) red[w] += red[w + 80];
    __syncthreads();
    if (w < 40) red[w] += red[w + 40];
    __syncthreads();
    if (w < 20) red[w] += red[w + 20];
    __syncthreads();
    if (w < 10) red[w] += red[w + 10];
    __syncthreads();
    if (w < 5) red[w] += red[w + 5];
    __syncthreads();
    if (w == 0) {
        g_l1part[bx] = red[0] + red[1] + red[2] + red[3] + red[4];
    }
}

// ---------------------------------------------------------------------------
// Kernel B: box-sum along D + SSIM per voxel + block reduction.
// 320 threads per block: two h-rows (ty = tid/160), one w each.
// grid = B * HPAIRS * K3_SEGS; each block handles a 40-deep d segment.
// ---------------------------------------------------------------------------
__global__ __launch_bounds__(K3_THREADS) void kB_dpass_ssim() {
    __shared__ float red[K3_THREADS];

    const int bid = blockIdx.x;
    const int seg = bid % K3_SEGS;
    const int hp = (bid / K3_SEGS) % HPAIRS;
    const int b = bid / (K3_SEGS * HPAIRS);

    const int tid = threadIdx.x;
    const int w = tid % W;
    const int ty = tid / W;            // 0 or 1
    const int h = hp * 2 + ty;

    const int d0 = seg * K3_SEGLEN;
    const int colbase = b * (D * HW) + h * W + w;

    const float* __restrict__ p0 = g_bufB + 0 * NVOX;
    const float* __restrict__ p1 = g_bufB + 1 * NVOX;
    const float* __restrict__ p2 = g_bufB + 2 * NVOX;
    const float* __restrict__ p3 = g_bufB + 3 * NVOX;
    const float* __restrict__ p4 = g_bufB + 4 * NVOX;

    float s0 = 0.f, s1 = 0.f, s2 = 0.f, s3 = 0.f, s4 = 0.f;
    {
        int lo = d0 - 5;
        if (lo < 0) lo = 0;
        int hi = d0 + 5;
        if (hi > D - 1) hi = D - 1;
        for (int d = lo; d <= hi; d++) {
            int id = colbase + d * HW;
            s0 += p0[id];
            s1 += p1[id];
            s2 += p2[id];
            s3 += p3[id];
            s4 += p4[id];
        }
    }

    float acc = 0.f;
#pragma unroll 4
    for (int i = 0; i < K3_SEGLEN; i++) {
        const int d = d0 + i;
        const int dn = d + 6;
        const int dp = d - 5;

        // issue window-edge loads first so they overlap the SSIM math
        float a0 = 0.f, a1 = 0.f, a2 = 0.f, a3 = 0.f, a4 = 0.f;
        float b0 = 0.f, b1 = 0.f, b2 = 0.f, b3 = 0.f, b4 = 0.f;
        if (dn < D) {
            int id = colbase + dn * HW;
            a0 = p0[id]; a1 = p1[id]; a2 = p2[id]; a3 = p3[id]; a4 = p4[id];
        }
        if (dp >= 0) {
            int id = colbase + dp * HW;
            b0 = p0[id]; b1 = p1[id]; b2 = p2[id]; b3 = p3[id]; b4 = p4[id];
        }

        float mux = s0 * INV_WIN3;
        float muy = s1 * INV_WIN3;
        float mux2 = mux * mux;
        float muy2 = muy * muy;
        float muxy = mux * muy;
        float sxx = s2 * INV_WIN3 - mux2;
        float syy = s3 * INV_WIN3 - muy2;
        float sxy = s4 * INV_WIN3 - muxy;
        float num = (2.f * muxy + C1F) * (2.f * sxy + C2F);
        float den = (mux2 + muy2 + C1F) * (sxx + syy + C2F);
        float ssim = num / (den + 1e-8f);
        float loss = (1.f - ssim) * 0.5f;
        loss = fminf(fmaxf(loss, 0.f), 1.f);
        acc += loss;

        s0 += a0 - b0;
        s1 += a1 - b1;
        s2 += a2 - b2;
        s3 += a3 - b3;
        s4 += a4 - b4;
    }

    // deterministic block reduction over 320 threads
    red[tid] = acc;
    __syncthreads();
    if (tid < 160) red[tid] += red[tid + 160];
    __syncthreads();
    if (tid < 80) red[tid] += red[tid + 80];
    __syncthreads();
    if (tid < 40) red[tid] += red[tid + 40];
    __syncthreads();
    if (tid < 20) red[tid] += red[tid + 20];
    __syncthreads();
    if (tid < 10) red[tid] += red[tid + 10];
    __syncthreads();
    if (tid < 5) red[tid] += red[tid + 5];
    __syncthreads();
    if (tid == 0) {
        g_ssimpart[bid] = red[0] + red[1] + red[2] + red[3] + red[4];
    }
}

// ---------------------------------------------------------------------------
// Kernel C: final deterministic reduction.
// ---------------------------------------------------------------------------
__global__ __launch_bounds__(256) void kC_final(float* __restrict__ out) {
    __shared__ double sh[256];
    const int t = threadIdx.x;
    const int nssim = 2 * HPAIRS * K3_SEGS;   // 640

    double a = 0.0;
    for (int i = t; i < A_BLOCKS; i += 256) a += (double)g_l1part[i];
    double bsum = 0.0;
    for (int i = t; i < nssim; i += 256) bsum += (double)g_ssimpart[i];

    sh[t] = a;
    __syncthreads();
#pragma unroll
    for (int s = 128; s > 0; s >>= 1) {
        if (t < s) sh[t] += sh[t + s];
        __syncthreads();
    }
    double l1sum = sh[0];
    __syncthreads();

    sh[t] = bsum;
    __syncthreads();
#pragma unroll
    for (int s = 128; s > 0; s >>= 1) {
        if (t < s) sh[t] += sh[t + s];
        __syncthreads();
    }

    if (t == 0) {
        double ssimsum = sh[0];
        double n = (double)NVOX;
        out[0] = (float)(0.85 * (ssimsum / n) + 0.15 * (l1sum / n));
    }
}

// ---------------------------------------------------------------------------
extern "C" void kernel_launch(void* const* d_in, const int* in_sizes, int n_in,
                              void* d_out, int out_size) {
    const float* pred = (const float*)d_in[0];
    const float* target = (const float*)d_in[1];
    float* out = (float*)d_out;

    kA_wh<<<A_BLOCKS, W>>>(pred, target);
    kB_dpass_ssim<<<B * HPAIRS * K3_SEGS, K3_THREADS>>>();
    kC_final<<<1, 256>>>(out);
}